// round 6
// baseline (speedup 1.0000x reference)
#include <cuda_runtime.h>
#include <cuda_bf16.h>
#include <cstdint>

// CTC forward negative log-likelihood (keras ctc_batch_cost semantics).
// B=128, T=1024, V=512, L=128, S=2L+1=257, blank=V-1.
//
// Round-5 design ("checkerboard registers"):
//  - 1 CTA per batch (grid=128), 128 threads (4 warps).
//  - Thread k owns states 2k (even/blank) and 2k+1 (odd/label); alpha kept in
//    REGISTERS. The only cross-thread dependency per step is old_odd[k-1]:
//    delivered via __shfl_up (software-pipelined: issued right after new_odd is
//    computed, consumed next step). Lane-0 reads a parity-double-buffered
//    4-entry shared halo from the previous warp.
//  - Even (blank) states share ONE probability p_blank = Y[b][t][V-1]
//    (LDS broadcast); odd states gather their label prob. Both are prefetched
//    one step ahead, so no LDS sits on the critical chain.
//  - Full 2KB probability row staged per step into a 16-deep shared ring via
//    coalesced cp.async.cg (128 threads x 16B). wait_group<D-3> guarantees row
//    t+1 is visible one barrier early (enables the p-prefetch).
//  - ONE __syncthreads per step. log2-domain recursion (raw ex2/lg2.approx),
//    final scaled by ln2.

#define NEGV (-1e30f)
#define EPSV (1e-7f)
#define LN2F (0.6931471805599453f)

constexpr int Bc = 128;
constexpr int Tc = 1024;
constexpr int Vc = 512;
constexpr int Lc = 128;
constexpr int Sc = 257;     // 2L+1
constexpr int D  = 16;      // ring stages (32KB)
constexpr int NT = 128;     // 4 warps

__device__ __forceinline__ float ex2f(float x) {
    float r; asm("ex2.approx.f32 %0, %1;" : "=f"(r) : "f"(x)); return r;
}
__device__ __forceinline__ float lg2f(float x) {
    float r; asm("lg2.approx.f32 %0, %1;" : "=f"(r) : "f"(x)); return r;
}
__device__ __forceinline__ void cp_async16(uint32_t saddr, const void* gptr) {
    asm volatile("cp.async.cg.shared.global [%0], [%1], 16;" :: "r"(saddr), "l"(gptr));
}
__device__ __forceinline__ void cp_commit() {
    asm volatile("cp.async.commit_group;");
}
template<int N>
__device__ __forceinline__ void cp_wait() {
    asm volatile("cp.async.wait_group %0;" :: "n"(N));
}

__global__ __launch_bounds__(NT, 1)
void ctc_forward_kernel(const int*   __restrict__ labels,     // [B, L]
                        const int*   __restrict__ lab_len,    // [B, 1]
                        const float* __restrict__ Y,          // [B, T, V]
                        const int*   __restrict__ in_len,     // [B, 1]
                        float*       __restrict__ out)        // [B, 1]
{
    __shared__ float rows[D][Vc];        // staged probability rows (32KB)
    __shared__ float halo[2][4];         // per-warp old_odd (lane31), by parity
    __shared__ int   lab_sh[Lc];
    __shared__ float alpha_fin[Sc + 3];  // final alphas for epilogue

    const int b    = blockIdx.x;
    const int tid  = threadIdx.x;
    const int wid  = tid >> 5;
    const int lane = tid & 31;

    lab_sh[tid] = labels[b * Lc + tid];
    const int len = in_len[b];

    if (tid < 8) halo[tid >> 2][tid & 3] = NEGV;

    const float* __restrict__ Yb = Y + (size_t)b * Tc * Vc;

    // ---- prologue: stage rows 0..D-1 ----
    #pragma unroll
    for (int j = 0; j < D; j++) {
        uint32_t sa = (uint32_t)__cvta_generic_to_shared(&rows[j][tid * 4]);
        int tr = (j < len) ? j : (len > 0 ? len - 1 : 0);
        cp_async16(sa, Yb + (size_t)tr * Vc + tid * 4);
        cp_commit();
    }
    cp_wait<D - 3>();                 // rows 0..2 complete
    __syncthreads();                  // labels, halo init, rows visible

    // ---- roles ----
    const int  k      = tid;          // owns states 2k, 2k+1
    const int  blank  = Vc - 1;
    const int  cls    = lab_sh[k];
    const bool cs     = (k > 0) && (cls != blank) && (cls != lab_sh[k - 1]);
    const bool isLast = (tid == NT - 1);   // also owns state 256

    float aE   = (k == 0) ? 0.0f : NEGV;   // log2 domain
    float aO   = NEGV;
    float a256 = NEGV;

    // prefetch for t=0
    float pO = rows[0][cls];
    float pB = rows[0][blank];
    float nb = __shfl_up_sync(0xffffffffu, aO, 1);  // old_odd[k-1], lanes>=1
    int par = 0;

    // ---- main recursion ----
    for (int t = 0; t < len; ++t) {
        // resolve cross-warp neighbor for lane 0
        float nbv = nb;
        if (lane == 0) nbv = (wid > 0) ? halo[par][wid - 1] : NEGV;

        // even/blank state 2k:  terms {aE, nbv}
        const float mE  = fmaxf(aE, nbv);
        const float loE = fminf(aE, nbv);
        const float nE  = mE + lg2f((1.0f + ex2f(loE - mE)) * (pB + EPSV));

        // odd/label state 2k+1: terms {aO, aE, cs ? nbv : NEG}
        const float a2 = cs ? nbv : NEGV;
        const float hi = fmaxf(aO, aE);
        const float lo = fminf(aO, aE);
        const float m  = fmaxf(hi, a2);
        const float x  = fminf(hi, a2);
        const float nO = m + lg2f((1.0f + ex2f(lo - m) + ex2f(x - m)) * (pO + EPSV));

        // state 256 (lane 31, warp 3): terms {a256, aO(state 255)}
        if (isLast) {
            const float m2 = fmaxf(a256, aO);
            const float l2 = fminf(a256, aO);
            a256 = m2 + lg2f((1.0f + ex2f(l2 - m2)) * (pB + EPSV));
        }

        aE = nE; aO = nO;

        // publish halo for next step (opposite parity)
        if (lane == 31) halo[par ^ 1][wid] = nO;

        // prefetch next-step neighbor + probabilities (row t+1 already staged)
        nb = __shfl_up_sync(0xffffffffu, nO, 1);
        const int st1 = (t + 1) & (D - 1);
        pO = rows[st1][cls];
        pB = rows[st1][blank];

        cp_wait<D - 3>();
        __syncthreads();              // publish halo, retire reads of slot t
        if (t + D < len) {
            cp_async16((uint32_t)__cvta_generic_to_shared(&rows[t & (D - 1)][tid * 4]),
                       Yb + (size_t)(t + D) * Vc + tid * 4);
            cp_commit();
        }
        par ^= 1;
    }

    // ---- epilogue ----
    alpha_fin[2 * k]     = aE;
    alpha_fin[2 * k + 1] = aO;
    if (isLast) alpha_fin[256] = a256;
    __syncthreads();
    if (tid == 0) {
        const int   ll = lab_len[b];
        const float aL = alpha_fin[2 * ll];
        const float aP = alpha_fin[2 * ll - 1];
        const float mm = fmaxf(aL, aP);
        const float ql = fminf(aL, aP);
        out[b] = -LN2F * (mm + lg2f(1.0f + ex2f(ql - mm)));
    }
}

extern "C" void kernel_launch(void* const* d_in, const int* in_sizes, int n_in,
                              void* d_out, int out_size) {
    const int*   labels  = (const int*)d_in[0];   // true_labels [B, L]
    const int*   lab_len = (const int*)d_in[1];   // true_lengths [B, 1]
    const float* Y       = (const float*)d_in[2]; // predicted_labels [B, T, V]
    const int*   in_len  = (const int*)d_in[3];   // predicted_lengths [B, 1]
    float*       out     = (float*)d_out;         // [B, 1]

    ctc_forward_kernel<<<Bc, NT>>>(labels, lab_len, Y, in_len, out);
}